// round 12
// baseline (speedup 1.0000x reference)
#include <cuda_runtime.h>
#include <cstdint>

// GAE reverse scan: 2-way truncated-halo split + cp.async SMEM pipeline,
// refill-before-wait ordering.
// Pipeline order per stage is now: FILL(next) -> commit -> wait_group -> consume
// -> syncwarp. The refill targets a slot freed last iteration, so it must not
// sit behind the DRAM-latency wait_group: issuing it first keeps DEPTH (not
// DEPTH-1) stages in flight and removes a request bubble per stage.
// wait_group(DEPTH-1) after commit == oldest stage arrived (same guarantee).
// Trailing __syncwarp protects the to-be-refilled slot across iterations.
//
// Everything else is the converged optimum (R5/R8/R10/R11 family):
// 512 blocks (grid 256x2), NCOL=64 (2 warps, warp-private columns), DEPTH=5
// (40KB static smem), cp.async.cg 16B reads, st.global.cs streaming writes,
// cost-balanced split M=464 with halo W=160 (rel_err ~1.7e-4, gate 1e-3).
// Do NOT re-add chunks or shrink blocks: R4/R6/R9 all regressed.

#define T_DIM    1024
#define B_DIM    16384
#define GAMMA    0.99f
#define COEF     (0.99f * 0.97f)
#define UNR      16          // time rows per stage
#define NCOL     64          // columns per block (two warps, warp-private 32)
#define DEPTH    5           // ring stages (40KB static smem)
#define M_SPLIT  464         // bottom writes [0,464); top writes [464,1024)
#define B_HI     624         // bottom scan top = M_SPLIT + 160 halo
#define NST_BOT  39          // 624 / UNR
#define NST_TOP  35          // (1024 - 464) / UNR

__device__ __forceinline__ uint32_t smem_u32(const void* p) {
    return (uint32_t)__cvta_generic_to_shared(p);
}

// Fill stage k_: warp w copies rows 0..15 x columns [32w,32w+32) of v and r.
// Per thread 4 float4 per array: row = lane/8 + 4j, col = 32w + (lane&7)*4.
#define FILL_STAGE(k_)                                                        \
    {                                                                         \
        const int ts_   = t_hi - UNR * ((k_) + 1);                            \
        const int slot_ = (k_) % DEPTH;                                       \
        const uint32_t svb = smem_u32(&sv[slot_][0]);                         \
        const uint32_t srb = smem_u32(&sr[slot_][0]);                         \
        _Pragma("unroll")                                                     \
        for (int j = 0; j < 4; j++) {                                         \
            const int row  = (lane >> 3) + 4 * j;                             \
            const int col  = wbase + (lane & 7) * 4;                          \
            const int flat = row * NCOL + col;     /* float index in tile */  \
            const size_t g = (size_t)(ts_ + row) * B_DIM + cb + col;          \
            asm volatile("cp.async.cg.shared.global [%0], [%1], 16;"          \
                         :: "r"(svb + flat * 4), "l"(value + g));             \
            asm volatile("cp.async.cg.shared.global [%0], [%1], 16;"          \
                         :: "r"(srb + flat * 4), "l"(reward + g));            \
        }                                                                     \
    }

__global__ void __launch_bounds__(NCOL) gae_kernel(
    const float* __restrict__ value,   // (T+1, B)
    const float* __restrict__ reward,  // (T, B)
    float* __restrict__ adv)           // (T, B)
{
    __shared__ float sv[DEPTH][UNR * NCOL];   // 20KB
    __shared__ float sr[DEPTH][UNR * NCOL];   // 20KB

    const int tid   = threadIdx.x;
    const int lane  = tid & 31;
    const int wbase = tid & 32;               // 0 or 32: this warp's column base
    const int cb    = blockIdx.x * NCOL;
    const int b     = cb + tid;
    const bool top  = (blockIdx.y != 0);

    const int t_hi    = top ? T_DIM : B_HI;      // 1024 : 624 (scan top, excl)
    const int wlim    = top ? T_DIM : M_SPLIT;   // write rows with t < wlim
    const int nstages = top ? NST_TOP : NST_BOT; // 35 : 39

    float carry  = 0.0f;                       // exact (top) / truncated bottom
    float v_next = value[(size_t)t_hi * B_DIM + b];

    // Prologue: DEPTH-1 stages in flight before the loop.
    #pragma unroll
    for (int s = 0; s < DEPTH - 1; s++) {
        FILL_STAGE(s);
        asm volatile("cp.async.commit_group;");
    }

    for (int k = 0; k < nstages; k++) {
        // 1) Refill FIRST (slot (k-1)%DEPTH, freed last iteration and fenced
        //    by the trailing syncwarp) — issue DRAM requests before blocking.
        if (k + DEPTH - 1 < nstages) {
            FILL_STAGE(k + DEPTH - 1);
        }
        asm volatile("cp.async.commit_group;");   // empty tail groups keep counts aligned

        // 2) Now block until stage k has landed: after commit there are up to
        //    DEPTH groups pending; <= DEPTH-1 pending => oldest (k) complete.
        asm volatile("cp.async.wait_group %0;" :: "n"(DEPTH - 1));
        __syncwarp();   // intra-warp visibility of stage k's fills

        // 3) Consume stage k: time descending within the stage.
        const int  slot     = k % DEPTH;
        const int  ts       = t_hi - UNR * (k + 1);
        const bool do_write = (ts + UNR <= wlim);
        #pragma unroll
        for (int j = UNR - 1; j >= 0; j--) {
            const float vt = sv[slot][j * NCOL + tid];
            const float rt = sr[slot][j * NCOL + tid];
            const float delta = fmaf(GAMMA, v_next, rt) - vt;
            carry = fmaf(COEF, carry, delta);
            if (do_write)
                __stcs(&adv[(size_t)(ts + j) * B_DIM + b], carry);  // streaming write
            v_next = vt;
        }
        // 4) All lanes done reading slot k before anyone refills it next iter.
        __syncwarp();
    }
}

extern "C" void kernel_launch(void* const* d_in, const int* in_sizes, int n_in,
                              void* d_out, int out_size)
{
    const float* value  = (const float*)d_in[0];
    const float* reward = (const float*)d_in[1];
    float* adv = (float*)d_out;

    dim3 grid(B_DIM / NCOL, 2);   // (256, 2): columns x time-chunk
    gae_kernel<<<grid, NCOL>>>(value, reward, adv);
}

// round 13
// speedup vs baseline: 1.0894x; 1.0894x over previous
#include <cuda_runtime.h>
#include <cstdint>

// GAE reverse scan: SINGLE-chunk cp.async SMEM pipeline (no time split).
// LTS-cap audit: the 2-way halo split issued 222MB through LTS (7.05 TB/s at
// 31.5us == the ~6300 B/cyc chip LTS ceiling); halo re-reads cost full LTS
// bandwidth even when L2-absorbed. Dropping the split cuts issued bytes to
// the 201MB floor (-9.4%) and makes the scan exact (rel_err ~1e-7).
// Latency hiding no longer needs many warps: 256 blocks x 7 in-flight stages
// x 8KB = 14MB in flight (6x the BW-latency product).
// Proven shape kept: NCOL=64 (2 warps, warp-private columns), DEPTH=8 (64KB
// smem, 3/SM residency cap vs 1.73 needed), R11 wait->fill ordering,
// cp.async.cg 16B reads, st.global.cs streaming writes.

#define T_DIM    1024
#define B_DIM    16384
#define GAMMA    0.99f
#define COEF     (0.99f * 0.97f)
#define UNR      16          // time rows per stage
#define NCOL     64          // columns per block (two warps, warp-private 32)
#define DEPTH    8           // ring stages (64KB static smem, 7 in flight)
#define NSTAGES  64          // 1024 / UNR

__device__ __forceinline__ uint32_t smem_u32(const void* p) {
    return (uint32_t)__cvta_generic_to_shared(p);
}

// Fill stage k_: warp w copies rows 0..15 x columns [32w,32w+32) of v and r.
// Per thread 4 float4 per array: row = lane/8 + 4j, col = 32w + (lane&7)*4.
#define FILL_STAGE(k_)                                                        \
    {                                                                         \
        const int ts_   = T_DIM - UNR * ((k_) + 1);                           \
        const int slot_ = (k_) % DEPTH;                                       \
        const uint32_t svb = smem_u32(&sv[slot_][0]);                         \
        const uint32_t srb = smem_u32(&sr[slot_][0]);                         \
        _Pragma("unroll")                                                     \
        for (int j = 0; j < 4; j++) {                                         \
            const int row  = (lane >> 3) + 4 * j;                             \
            const int col  = wbase + (lane & 7) * 4;                          \
            const int flat = row * NCOL + col;     /* float index in tile */  \
            const size_t g = (size_t)(ts_ + row) * B_DIM + cb + col;          \
            asm volatile("cp.async.cg.shared.global [%0], [%1], 16;"          \
                         :: "r"(svb + flat * 4), "l"(value + g));             \
            asm volatile("cp.async.cg.shared.global [%0], [%1], 16;"          \
                         :: "r"(srb + flat * 4), "l"(reward + g));            \
        }                                                                     \
    }

__global__ void __launch_bounds__(NCOL) gae_kernel(
    const float* __restrict__ value,   // (T+1, B)
    const float* __restrict__ reward,  // (T, B)
    float* __restrict__ adv)           // (T, B)
{
    __shared__ float sv[DEPTH][UNR * NCOL];   // 32KB
    __shared__ float sr[DEPTH][UNR * NCOL];   // 32KB

    const int tid   = threadIdx.x;
    const int lane  = tid & 31;
    const int wbase = tid & 32;               // 0 or 32: this warp's column base
    const int cb    = blockIdx.x * NCOL;
    const int b     = cb + tid;

    float carry  = 0.0f;                       // exact: scan starts at t = T
    float v_next = value[(size_t)T_DIM * B_DIM + b];

    // Prologue: DEPTH-1 stages in flight before any compute.
    #pragma unroll
    for (int s = 0; s < DEPTH - 1; s++) {
        FILL_STAGE(s);
        asm volatile("cp.async.commit_group;");
    }

    for (int k = 0; k < NSTAGES; k++) {
        // Stage k complete when <= DEPTH-2 of this warp's groups pending.
        asm volatile("cp.async.wait_group %0;" :: "n"(DEPTH - 2));
        __syncwarp();   // columns are warp-private: intra-warp visibility only

        // Refill the slot freed by stage k-1 (this warp's own columns).
        if (k + DEPTH - 1 < NSTAGES) {
            FILL_STAGE(k + DEPTH - 1);
        }
        asm volatile("cp.async.commit_group;");   // empty tail groups keep counts aligned

        // Consume stage k: time descending within the stage.
        const int slot = k % DEPTH;
        const int ts   = T_DIM - UNR * (k + 1);
        #pragma unroll
        for (int j = UNR - 1; j >= 0; j--) {
            const float vt = sv[slot][j * NCOL + tid];
            const float rt = sr[slot][j * NCOL + tid];
            const float delta = fmaf(GAMMA, v_next, rt) - vt;
            carry = fmaf(COEF, carry, delta);
            __stcs(&adv[(size_t)(ts + j) * B_DIM + b], carry);  // streaming write
            v_next = vt;
        }
        __syncwarp();
    }
}

extern "C" void kernel_launch(void* const* d_in, const int* in_sizes, int n_in,
                              void* d_out, int out_size)
{
    const float* value  = (const float*)d_in[0];
    const float* reward = (const float*)d_in[1];
    float* adv = (float*)d_out;

    gae_kernel<<<B_DIM / NCOL, NCOL>>>(value, reward, adv);   // 256 blocks
}